// round 1
// baseline (speedup 1.0000x reference)
#include <cuda_runtime.h>
#include <math.h>

#define NN 128
#define MM 64
#define ROWPAD 65   // 65-float row stride: bank = (i + j) % 32, conflict-free across rows

__device__ __forceinline__ float softplus_f(float x) {
    // log(1 + exp(x)), stable
    return x > 0.f ? x + log1pf(expf(-x)) : log1pf(expf(x));
}

__device__ __forceinline__ float warp_sum(float v) {
    #pragma unroll
    for (int o = 16; o > 0; o >>= 1) v += __shfl_xor_sync(0xffffffffu, v, o);
    return v;
}

__device__ __forceinline__ float warp_max(float v) {
    #pragma unroll
    for (int o = 16; o > 0; o >>= 1) v = fmaxf(v, __shfl_xor_sync(0xffffffffu, v, o));
    return v;
}

__global__ __launch_bounds__(128) void rom_kernel(
    const float* __restrict__ memory,   // [B, N, M]
    const float* __restrict__ key,      // [B, M]
    const float* __restrict__ beta_in,  // [B, 1]
    const float* __restrict__ g_in,     // [B, 1]
    const float* __restrict__ s_in,     // [B, 3]
    const float* __restrict__ gamma_in, // [B, 1]
    const float* __restrict__ w_prev,   // [B, N]
    float* __restrict__ out)            // [B, N]
{
    __shared__ float sh[NN * ROWPAD];   // padded memory tile
    __shared__ float shk[MM];           // key (+1e-16)
    __shared__ float shw[NN];           // interpolated weighting wg
    __shared__ float redA[4], redB[4];  // cross-warp reduction scratch
    __shared__ float par[6];            // beta, g, s0, s1, s2, gamma

    const int b    = blockIdx.x;
    const int tid  = threadIdx.x;
    const int lane = tid & 31;
    const int wid  = tid >> 5;

    // ---- Stage memory tile: fully coalesced float4 loads ----
    const float4* mem4 = reinterpret_cast<const float4*>(memory) + (size_t)b * (NN * MM / 4);
    #pragma unroll
    for (int it = 0; it < 16; ++it) {
        int idx = tid + it * 128;          // float4 index within tile
        float4 v = mem4[idx];
        int row = idx >> 4;                // 16 float4 per row (M=64)
        int col = (idx & 15) << 2;
        float* dst = &sh[row * ROWPAD + col];
        dst[0] = v.x + 1e-16f;
        dst[1] = v.y + 1e-16f;
        dst[2] = v.z + 1e-16f;
        dst[3] = v.w + 1e-16f;
    }
    if (tid < 16) {
        float4 v = reinterpret_cast<const float4*>(key + (size_t)b * MM)[tid];
        shk[tid * 4 + 0] = v.x + 1e-16f;
        shk[tid * 4 + 1] = v.y + 1e-16f;
        shk[tid * 4 + 2] = v.z + 1e-16f;
        shk[tid * 4 + 3] = v.w + 1e-16f;
    }
    if (tid == 0) {
        par[0] = softplus_f(beta_in[b]);                 // beta
        par[1] = 1.f / (1.f + expf(-g_in[b]));           // g (sigmoid)
        float s0 = s_in[b * 3 + 0], s1 = s_in[b * 3 + 1], s2 = s_in[b * 3 + 2];
        float sm = fmaxf(s0, fmaxf(s1, s2));
        float e0 = expf(s0 - sm), e1 = expf(s1 - sm), e2 = expf(s2 - sm);
        float inv = 1.f / (e0 + e1 + e2);
        par[2] = e0 * inv; par[3] = e1 * inv; par[4] = e2 * inv;
        par[5] = 1.f + softplus_f(gamma_in[b]);          // gamma
    }
    __syncthreads();

    // ---- Per-row cosine similarity (thread tid owns row tid) ----
    float dot = 0.f, nrm = 0.f, kn = 0.f;
    const float* row = &sh[tid * ROWPAD];
    #pragma unroll
    for (int j = 0; j < MM; ++j) {
        float m = row[j];
        float kv = shk[j];
        dot += m * kv;
        nrm += m * m;
        kn  += kv * kv;   // redundant per thread; avoids an extra reduction
    }
    float mem_norm = fmaxf(sqrtf(nrm), 1e-8f);
    float key_norm = fmaxf(sqrtf(kn), 1e-8f);
    float z = par[0] * (dot / (mem_norm * key_norm));

    // ---- Block softmax over N=128 ----
    float mx = warp_max(z);
    if (lane == 0) redA[wid] = mx;
    __syncthreads();
    float mz = fmaxf(fmaxf(redA[0], redA[1]), fmaxf(redA[2], redA[3]));
    float e = expf(z - mz);
    float se = warp_sum(e);
    if (lane == 0) redB[wid] = se;
    __syncthreads();
    float tot = redB[0] + redB[1] + redB[2] + redB[3];
    float wc = e / tot;

    // ---- Interpolate ----
    float g = par[1];
    float wg = g * wc + (1.f - g) * w_prev[(size_t)b * NN + tid];
    shw[tid] = wg;
    __syncthreads();

    // ---- Circular 3-tap shift ----
    float wh = shw[(tid + NN - 1) & (NN - 1)] * par[2]
             + wg * par[3]
             + shw[(tid + 1) & (NN - 1)] * par[4];

    // ---- Sharpen + normalize ----
    float w = powf(wh, par[5]);
    float sw = warp_sum(w);
    if (lane == 0) redA[wid] = sw;   // redA safe to reuse: last read was before the shw sync
    __syncthreads();
    float tw = redA[0] + redA[1] + redA[2] + redA[3] + 1e-16f;

    out[(size_t)b * NN + tid] = w / tw;
}

extern "C" void kernel_launch(void* const* d_in, const int* in_sizes, int n_in,
                              void* d_out, int out_size) {
    const float* memory  = (const float*)d_in[0];  // [B, N, M]
    const float* k       = (const float*)d_in[1];  // [B, M]
    const float* beta    = (const float*)d_in[2];  // [B, 1]
    const float* g       = (const float*)d_in[3];  // [B, 1]
    const float* s       = (const float*)d_in[4];  // [B, 3]
    const float* gamma   = (const float*)d_in[5];  // [B, 1]
    const float* w_prev  = (const float*)d_in[6];  // [B, N]
    float* out = (float*)d_out;

    int B = in_sizes[0] / (NN * MM);
    rom_kernel<<<B, 128>>>(memory, k, beta, g, s, gamma, w_prev, out);
}

// round 2
// speedup vs baseline: 1.1574x; 1.1574x over previous
#include <cuda_runtime.h>
#include <math.h>

#define NN 128
#define MM 64

__device__ __forceinline__ float softplus_f(float x) {
    return x > 0.f ? x + log1pf(expf(-x)) : log1pf(expf(x));
}

__device__ __forceinline__ float warp_sum(float v) {
    #pragma unroll
    for (int o = 16; o > 0; o >>= 1) v += __shfl_xor_sync(0xffffffffu, v, o);
    return v;
}

__device__ __forceinline__ float warp_max(float v) {
    #pragma unroll
    for (int o = 16; o > 0; o >>= 1) v = fmaxf(v, __shfl_xor_sync(0xffffffffu, v, o));
    return v;
}

__global__ __launch_bounds__(128) void rom_kernel(
    const float* __restrict__ memory,   // [B, N, M]
    const float* __restrict__ key,      // [B, M]
    const float* __restrict__ beta_in,  // [B, 1]
    const float* __restrict__ g_in,     // [B, 1]
    const float* __restrict__ s_in,     // [B, 3]
    const float* __restrict__ gamma_in, // [B, 1]
    const float* __restrict__ w_prev,   // [B, N]
    float* __restrict__ out)            // [B, N]
{
    __shared__ float shz[NN];           // raw cosine (pre-beta) per row
    __shared__ float shw[NN];           // interpolated weighting wg
    __shared__ float redA[4], redB[4];  // cross-warp reduction scratch
    __shared__ float par[6];            // beta, g, s0, s1, s2, gamma

    const int b    = blockIdx.x;
    const int tid  = threadIdx.x;
    const int lane = tid & 31;
    const int wid  = tid >> 5;
    const int sub  = tid & 15;          // float4-chunk index within a row
    const int rsub = tid >> 4;          // row-within-iteration (0..7)

    if (tid == 0) {
        par[0] = softplus_f(beta_in[b]);                 // beta
        par[1] = 1.f / (1.f + expf(-g_in[b]));           // g (sigmoid)
        float s0 = s_in[b * 3 + 0], s1 = s_in[b * 3 + 1], s2 = s_in[b * 3 + 2];
        float sm = fmaxf(s0, fmaxf(s1, s2));
        float e0 = expf(s0 - sm), e1 = expf(s1 - sm), e2 = expf(s2 - sm);
        float inv = 1.f / (e0 + e1 + e2);
        par[2] = e0 * inv; par[3] = e1 * inv; par[4] = e2 * inv;
        par[5] = 1.f + softplus_f(gamma_in[b]);          // gamma
    }

    // ---- Key chunk: loaded once into registers (broadcast across the two
    //      16-lane groups of each warp; L1-served) ----
    float4 kv = reinterpret_cast<const float4*>(key + (size_t)b * MM)[sub];
    kv.x += 1e-16f; kv.y += 1e-16f; kv.z += 1e-16f; kv.w += 1e-16f;

    float knp = kv.x * kv.x + kv.y * kv.y + kv.z * kv.z + kv.w * kv.w;
    #pragma unroll
    for (int o = 8; o > 0; o >>= 1) knp += __shfl_xor_sync(0xffffffffu, knp, o);
    const float key_norm = fmaxf(sqrtf(knp), 1e-8f);
    const float inv_kn   = 1.f / key_norm;

    // ---- Cosine similarity straight from global: 16 lanes per row,
    //      8 rows / iteration, 16 iterations. Fully coalesced LDG.128. ----
    const float4* mem4 = reinterpret_cast<const float4*>(memory)
                       + (size_t)b * (NN * MM / 4);
    #pragma unroll
    for (int it = 0; it < 16; ++it) {
        float4 v = mem4[it * 128 + tid];
        float dp = v.x * kv.x + v.y * kv.y + v.z * kv.z + v.w * kv.w;
        float np = v.x * v.x  + v.y * v.y  + v.z * v.z  + v.w * v.w;
        #pragma unroll
        for (int o = 8; o > 0; o >>= 1) {
            dp += __shfl_xor_sync(0xffffffffu, dp, o);
            np += __shfl_xor_sync(0xffffffffu, np, o);
        }
        if (sub == 0) {
            float mem_norm = fmaxf(sqrtf(np), 1e-8f);
            shz[it * 8 + rsub] = dp / mem_norm * inv_kn;
        }
    }
    __syncthreads();

    // ---- Block softmax over N=128 (thread tid owns row tid) ----
    float z = par[0] * shz[tid];
    float mx = warp_max(z);
    if (lane == 0) redA[wid] = mx;
    __syncthreads();
    float mz = fmaxf(fmaxf(redA[0], redA[1]), fmaxf(redA[2], redA[3]));
    float e = expf(z - mz);
    float se = warp_sum(e);
    if (lane == 0) redB[wid] = se;
    __syncthreads();
    float tot = redB[0] + redB[1] + redB[2] + redB[3];
    float wc = e / tot;

    // ---- Interpolate ----
    float g = par[1];
    float wg = g * wc + (1.f - g) * w_prev[(size_t)b * NN + tid];
    shw[tid] = wg;
    __syncthreads();

    // ---- Circular 3-tap shift ----
    float wh = shw[(tid + NN - 1) & (NN - 1)] * par[2]
             + wg * par[3]
             + shw[(tid + 1) & (NN - 1)] * par[4];

    // ---- Sharpen + normalize ----
    float w = powf(wh, par[5]);
    float sw = warp_sum(w);
    if (lane == 0) redA[wid] = sw;
    __syncthreads();
    float tw = redA[0] + redA[1] + redA[2] + redA[3] + 1e-16f;

    out[(size_t)b * NN + tid] = w / tw;
}

extern "C" void kernel_launch(void* const* d_in, const int* in_sizes, int n_in,
                              void* d_out, int out_size) {
    const float* memory  = (const float*)d_in[0];  // [B, N, M]
    const float* k       = (const float*)d_in[1];  // [B, M]
    const float* beta    = (const float*)d_in[2];  // [B, 1]
    const float* g       = (const float*)d_in[3];  // [B, 1]
    const float* s       = (const float*)d_in[4];  // [B, 3]
    const float* gamma   = (const float*)d_in[5];  // [B, 1]
    const float* w_prev  = (const float*)d_in[6];  // [B, N]
    float* out = (float*)d_out;

    int B = in_sizes[0] / (NN * MM);
    rom_kernel<<<B, 128>>>(memory, k, beta, g, s, gamma, w_prev, out);
}

// round 3
// speedup vs baseline: 1.3835x; 1.1953x over previous
#include <cuda_runtime.h>
#include <math.h>

#define NN 128
#define MM 64

__device__ __forceinline__ float softplus_f(float x) {
    return x > 0.f ? x + log1pf(expf(-x)) : log1pf(expf(x));
}

__device__ __forceinline__ float warp_sum(float v) {
    #pragma unroll
    for (int o = 16; o > 0; o >>= 1) v += __shfl_xor_sync(0xffffffffu, v, o);
    return v;
}

__device__ __forceinline__ float warp_max(float v) {
    #pragma unroll
    for (int o = 16; o > 0; o >>= 1) v = fmaxf(v, __shfl_xor_sync(0xffffffffu, v, o));
    return v;
}

__global__ __launch_bounds__(128) void rom_kernel(
    const float* __restrict__ memory,   // [B, N, M]
    const float* __restrict__ key,      // [B, M]
    const float* __restrict__ beta_in,  // [B, 1]
    const float* __restrict__ g_in,     // [B, 1]
    const float* __restrict__ s_in,     // [B, 3]
    const float* __restrict__ gamma_in, // [B, 1]
    const float* __restrict__ w_prev,   // [B, N]
    float* __restrict__ out)            // [B, N]
{
    __shared__ float shz[NN];           // raw cosine (pre-beta) per row
    __shared__ float shw[NN];           // interpolated weighting wg
    __shared__ float redA[4], redB[4];  // cross-warp reduction scratch
    __shared__ float par[6];            // beta, g, s0, s1, s2, gamma

    const int b    = blockIdx.x;
    const int tid  = threadIdx.x;
    const int lane = tid & 31;
    const int wid  = tid >> 5;
    const int l    = tid & 7;           // lane within 8-lane row group
    const int rg   = tid >> 3;          // row group (0..15)

    if (tid == 0) {
        par[0] = softplus_f(beta_in[b]);                 // beta
        par[1] = 1.f / (1.f + __expf(-g_in[b]));         // g (sigmoid)
        float s0 = s_in[b * 3 + 0], s1 = s_in[b * 3 + 1], s2 = s_in[b * 3 + 2];
        float sm = fmaxf(s0, fmaxf(s1, s2));
        float e0 = __expf(s0 - sm), e1 = __expf(s1 - sm), e2 = __expf(s2 - sm);
        float inv = 1.f / (e0 + e1 + e2);
        par[2] = e0 * inv; par[3] = e1 * inv; par[4] = e2 * inv;
        par[5] = 1.f + softplus_f(gamma_in[b]);          // gamma
    }

    // ---- Key chunks for this thread's lane position (chunks l and l+8) ----
    const float4* key4 = reinterpret_cast<const float4*>(key + (size_t)b * MM);
    float4 k0 = key4[l];
    float4 k1 = key4[l + 8];

    // key norm: 8-lane groups cover all 16 chunks
    float knp = k0.x * k0.x + k0.y * k0.y + k0.z * k0.z + k0.w * k0.w
              + k1.x * k1.x + k1.y * k1.y + k1.z * k1.z + k1.w * k1.w;
    #pragma unroll
    for (int o = 4; o > 0; o >>= 1) knp += __shfl_xor_sync(0xffffffffu, knp, o);
    const float inv_kn = 1.f / fmaxf(sqrtf(knp), 1e-8f);

    // ---- Cosine similarity: 8 lanes per row, 16 rows per pass, 8 passes.
    //      Each 8-lane group reads one contiguous 128B line per LDG. ----
    const float4* mem4 = reinterpret_cast<const float4*>(memory)
                       + (size_t)b * (NN * MM / 4);
    #pragma unroll
    for (int p = 0; p < 8; ++p) {
        const int row = p * 16 + rg;
        float4 v0 = mem4[row * 16 + l];
        float4 v1 = mem4[row * 16 + l + 8];

        float dp = v0.x * k0.x + v0.y * k0.y + v0.z * k0.z + v0.w * k0.w
                 + v1.x * k1.x + v1.y * k1.y + v1.z * k1.z + v1.w * k1.w;
        float np = v0.x * v0.x + v0.y * v0.y + v0.z * v0.z + v0.w * v0.w
                 + v1.x * v1.x + v1.y * v1.y + v1.z * v1.z + v1.w * v1.w;

        // Fused 8-lane reduction: lanes 0-3 reduce dp, lanes 4-7 reduce np.
        float send = (l & 4) ? dp : np;
        float recv = __shfl_xor_sync(0xffffffffu, send, 4);
        float v = ((l & 4) ? np : dp) + recv;
        v += __shfl_xor_sync(0xffffffffu, v, 2);
        v += __shfl_xor_sync(0xffffffffu, v, 1);
        float other = __shfl_xor_sync(0xffffffffu, v, 4);  // lane 0: np total

        if (l == 0) {
            float mem_norm = fmaxf(sqrtf(other), 1e-8f);
            shz[row] = (v / mem_norm) * inv_kn;
        }
    }
    __syncthreads();

    // ---- Block softmax over N=128 (thread tid owns row tid) ----
    float z = par[0] * shz[tid];
    float mx = warp_max(z);
    if (lane == 0) redA[wid] = mx;
    __syncthreads();
    float mz = fmaxf(fmaxf(redA[0], redA[1]), fmaxf(redA[2], redA[3]));
    float e = __expf(z - mz);
    float se = warp_sum(e);
    if (lane == 0) redB[wid] = se;
    __syncthreads();
    float tot = redB[0] + redB[1] + redB[2] + redB[3];
    float wc = e / tot;

    // ---- Interpolate ----
    float g = par[1];
    float wg = g * wc + (1.f - g) * w_prev[(size_t)b * NN + tid];
    shw[tid] = wg;
    __syncthreads();

    // ---- Circular 3-tap shift ----
    float wh = shw[(tid + NN - 1) & (NN - 1)] * par[2]
             + wg * par[3]
             + shw[(tid + 1) & (NN - 1)] * par[4];

    // ---- Sharpen + normalize ----
    float w = __powf(wh, par[5]);
    float sw = warp_sum(w);
    if (lane == 0) redA[wid] = sw;
    __syncthreads();
    float tw = redA[0] + redA[1] + redA[2] + redA[3] + 1e-16f;

    out[(size_t)b * NN + tid] = w / tw;
}

extern "C" void kernel_launch(void* const* d_in, const int* in_sizes, int n_in,
                              void* d_out, int out_size) {
    const float* memory  = (const float*)d_in[0];  // [B, N, M]
    const float* k       = (const float*)d_in[1];  // [B, M]
    const float* beta    = (const float*)d_in[2];  // [B, 1]
    const float* g       = (const float*)d_in[3];  // [B, 1]
    const float* s       = (const float*)d_in[4];  // [B, 3]
    const float* gamma   = (const float*)d_in[5];  // [B, 1]
    const float* w_prev  = (const float*)d_in[6];  // [B, N]
    float* out = (float*)d_out;

    int B = in_sizes[0] / (NN * MM);
    rom_kernel<<<B, 128>>>(memory, k, beta, g, s, gamma, w_prev, out);
}

// round 4
// speedup vs baseline: 1.3934x; 1.0072x over previous
#include <cuda_runtime.h>
#include <math.h>

#define NN 128
#define MM 64

__device__ __forceinline__ float softplus_f(float x) {
    return x > 0.f ? x + log1pf(expf(-x)) : log1pf(expf(x));
}

__device__ __forceinline__ float warp_sum(float v) {
    #pragma unroll
    for (int o = 16; o > 0; o >>= 1) v += __shfl_xor_sync(0xffffffffu, v, o);
    return v;
}

__device__ __forceinline__ float warp_max(float v) {
    #pragma unroll
    for (int o = 16; o > 0; o >>= 1) v = fmaxf(v, __shfl_xor_sync(0xffffffffu, v, o));
    return v;
}

__global__ __launch_bounds__(128) void rom_kernel(
    const float* __restrict__ memory,   // [B, N, M]
    const float* __restrict__ key,      // [B, M]
    const float* __restrict__ beta_in,  // [B, 1]
    const float* __restrict__ g_in,     // [B, 1]
    const float* __restrict__ s_in,     // [B, 3]
    const float* __restrict__ gamma_in, // [B, 1]
    const float* __restrict__ w_prev,   // [B, N]
    float* __restrict__ out)            // [B, N]
{
    __shared__ float shdp[NN * 8];      // per-row dot partials (xor-swizzled)
    __shared__ float shnp[NN * 8];      // per-row norm partials (xor-swizzled)
    __shared__ float shw[NN];           // interpolated weighting wg
    __shared__ float redA[4], redB[4];  // cross-warp reduction scratch
    __shared__ float par[6];            // beta, g, s0, s1, s2, gamma

    const int b    = blockIdx.x;
    const int tid  = threadIdx.x;
    const int lane = tid & 31;
    const int wid  = tid >> 5;
    const int l    = tid & 7;           // lane within 8-lane row group
    const int rg   = tid >> 3;          // row group (0..15)

    // ---- Prefetch w_prev early (independent DRAM load, overlapped) ----
    const float wp = w_prev[(size_t)b * NN + tid];

    if (tid == 0) {
        par[0] = softplus_f(beta_in[b]);                 // beta
        par[1] = 1.f / (1.f + __expf(-g_in[b]));         // g (sigmoid)
        float s0 = s_in[b * 3 + 0], s1 = s_in[b * 3 + 1], s2 = s_in[b * 3 + 2];
        float sm = fmaxf(s0, fmaxf(s1, s2));
        float e0 = __expf(s0 - sm), e1 = __expf(s1 - sm), e2 = __expf(s2 - sm);
        float inv = 1.f / (e0 + e1 + e2);
        par[2] = e0 * inv; par[3] = e1 * inv; par[4] = e2 * inv;
        par[5] = 1.f + softplus_f(gamma_in[b]);          // gamma
    }

    // ---- Key chunks for this thread's lane position (chunks l and l+8) ----
    const float4* key4 = reinterpret_cast<const float4*>(key + (size_t)b * MM);
    float4 k0 = key4[l];
    float4 k1 = key4[l + 8];

    // key norm: 8-lane groups cover all 16 chunks (prologue-only SHFLs)
    float knp = k0.x * k0.x + k0.y * k0.y + k0.z * k0.z + k0.w * k0.w
              + k1.x * k1.x + k1.y * k1.y + k1.z * k1.z + k1.w * k1.w;
    #pragma unroll
    for (int o = 4; o > 0; o >>= 1) knp += __shfl_xor_sync(0xffffffffu, knp, o);
    const float inv_kn = 1.f / fmaxf(sqrtf(knp), 1e-8f);

    // ---- Streaming loop: 8 lanes per row, 16 rows/pass, 8 passes.
    //      NO cross-lane ops: partials go to swizzled smem. All 16 LDG.128
    //      are independent -> front-batched, maximum MLP. ----
    const float4* mem4 = reinterpret_cast<const float4*>(memory)
                       + (size_t)b * (NN * MM / 4);
    const int sw = l ^ (rg & 7);        // row&7 == rg&7 (rows are p*16+rg)
    #pragma unroll
    for (int p = 0; p < 8; ++p) {
        const int row = p * 16 + rg;
        float4 v0 = mem4[row * 16 + l];
        float4 v1 = mem4[row * 16 + l + 8];

        float dp = v0.x * k0.x + v0.y * k0.y + v0.z * k0.z + v0.w * k0.w
                 + v1.x * k1.x + v1.y * k1.y + v1.z * k1.z + v1.w * k1.w;
        float np = v0.x * v0.x + v0.y * v0.y + v0.z * v0.z + v0.w * v0.w
                 + v1.x * v1.x + v1.y * v1.y + v1.z * v1.z + v1.w * v1.w;

        shdp[(row << 3) + sw] = dp;     // conflict-free STS (xor swizzle)
        shnp[(row << 3) + sw] = np;
    }
    __syncthreads();

    // ---- Per-row reduction: sum is order-independent, so read the
    //      swizzled row blindly as 2x float4. Thread tid owns row tid. ----
    const float4* dp4 = reinterpret_cast<const float4*>(&shdp[tid << 3]);
    const float4* np4 = reinterpret_cast<const float4*>(&shnp[tid << 3]);
    float4 d0 = dp4[0], d1 = dp4[1];
    float4 n0 = np4[0], n1 = np4[1];
    float dot = (d0.x + d0.y) + (d0.z + d0.w) + (d1.x + d1.y) + (d1.z + d1.w);
    float nrm = (n0.x + n0.y) + (n0.z + n0.w) + (n1.x + n1.y) + (n1.z + n1.w);

    float mem_norm = fmaxf(sqrtf(nrm), 1e-8f);
    float z = par[0] * ((dot / mem_norm) * inv_kn);

    // ---- Block softmax over N=128 ----
    float mx = warp_max(z);
    if (lane == 0) redA[wid] = mx;
    __syncthreads();
    float mz = fmaxf(fmaxf(redA[0], redA[1]), fmaxf(redA[2], redA[3]));
    float e = __expf(z - mz);
    float se = warp_sum(e);
    if (lane == 0) redB[wid] = se;
    __syncthreads();
    float tot = redB[0] + redB[1] + redB[2] + redB[3];
    float wc = e / tot;

    // ---- Interpolate ----
    float g = par[1];
    float wg = g * wc + (1.f - g) * wp;
    shw[tid] = wg;
    __syncthreads();

    // ---- Circular 3-tap shift ----
    float wh = shw[(tid + NN - 1) & (NN - 1)] * par[2]
             + wg * par[3]
             + shw[(tid + 1) & (NN - 1)] * par[4];

    // ---- Sharpen + normalize ----
    float w = __powf(wh, par[5]);
    float sw2 = warp_sum(w);
    if (lane == 0) redA[wid] = sw2;
    __syncthreads();
    float tw = redA[0] + redA[1] + redA[2] + redA[3] + 1e-16f;

    out[(size_t)b * NN + tid] = w / tw;
}

extern "C" void kernel_launch(void* const* d_in, const int* in_sizes, int n_in,
                              void* d_out, int out_size) {
    const float* memory  = (const float*)d_in[0];  // [B, N, M]
    const float* k       = (const float*)d_in[1];  // [B, M]
    const float* beta    = (const float*)d_in[2];  // [B, 1]
    const float* g       = (const float*)d_in[3];  // [B, 1]
    const float* s       = (const float*)d_in[4];  // [B, 3]
    const float* gamma   = (const float*)d_in[5];  // [B, 1]
    const float* w_prev  = (const float*)d_in[6];  // [B, N]
    float* out = (float*)d_out;

    int B = in_sizes[0] / (NN * MM);
    rom_kernel<<<B, 128>>>(memory, k, beta, g, s, gamma, w_prev, out);
}

// round 5
// speedup vs baseline: 1.4929x; 1.0714x over previous
#include <cuda_runtime.h>
#include <math.h>

#define NN 128
#define MM 64

__device__ __forceinline__ float softplus_f(float x) {
    return x > 0.f ? x + log1pf(expf(-x)) : log1pf(expf(x));
}

__device__ __forceinline__ float warp_sum(float v) {
    #pragma unroll
    for (int o = 16; o > 0; o >>= 1) v += __shfl_xor_sync(0xffffffffu, v, o);
    return v;
}

__device__ __forceinline__ float4 ldcs4(const float4* p) {
    return __ldcs(p);
}

__global__ __launch_bounds__(128, 8) void rom_kernel(
    const float* __restrict__ memory,   // [B, N, M]
    const float* __restrict__ key,      // [B, M]
    const float* __restrict__ beta_in,  // [B, 1]
    const float* __restrict__ g_in,     // [B, 1]
    const float* __restrict__ s_in,     // [B, 3]
    const float* __restrict__ gamma_in, // [B, 1]
    const float* __restrict__ w_prev,   // [B, N]
    float* __restrict__ out)            // [B, N]
{
    __shared__ float shdp[NN * 8];      // per-row dot partials (xor-swizzled)
    __shared__ float shnp[NN * 8];      // per-row norm partials (xor-swizzled)
    __shared__ float shw[NN];           // interpolated weighting wg
    __shared__ float redA[4], redB[4];  // cross-warp reduction scratch
    __shared__ float par[6];            // beta, g, s0, s1, s2, gamma

    const int b    = blockIdx.x;
    const int tid  = threadIdx.x;
    const int lane = tid & 31;
    const int wid  = tid >> 5;
    const int l    = tid & 7;           // lane within 8-lane row group
    const int rg   = tid >> 3;          // row group (0..15)

    // ---- Prefetch w_prev early (independent DRAM load, overlapped) ----
    const float wp = w_prev[(size_t)b * NN + tid];

    if (tid == 0) {
        par[0] = softplus_f(beta_in[b]);                 // beta
        par[1] = 1.f / (1.f + __expf(-g_in[b]));         // g (sigmoid)
        float s0 = s_in[b * 3 + 0], s1 = s_in[b * 3 + 1], s2 = s_in[b * 3 + 2];
        float sm = fmaxf(s0, fmaxf(s1, s2));
        float e0 = __expf(s0 - sm), e1 = __expf(s1 - sm), e2 = __expf(s2 - sm);
        float inv = 1.f / (e0 + e1 + e2);
        par[2] = e0 * inv; par[3] = e1 * inv; par[4] = e2 * inv;
        par[5] = 1.f + softplus_f(gamma_in[b]);          // gamma
    }

    // ---- Key chunks for this thread's lane position (chunks l and l+8) ----
    const float4* key4 = reinterpret_cast<const float4*>(key + (size_t)b * MM);
    float4 k0 = key4[l];
    float4 k1 = key4[l + 8];

    // key norm: 8-lane groups cover all 16 chunks (prologue-only SHFLs)
    float knp = k0.x * k0.x + k0.y * k0.y + k0.z * k0.z + k0.w * k0.w
              + k1.x * k1.x + k1.y * k1.y + k1.z * k1.z + k1.w * k1.w;
    #pragma unroll
    for (int o = 4; o > 0; o >>= 1) knp += __shfl_xor_sync(0xffffffffu, knp, o);
    const float inv_kn = 1.f / fmaxf(sqrtf(knp), 1e-8f);

    // ---- Streaming: 8 lanes per row. Two explicit 8-deep load batches so
    //      ptxas front-batches the LDG.128s (MLP_p1 = 8/thread). ----
    const float4* base = reinterpret_cast<const float4*>(memory)
                       + (size_t)b * (NN * MM / 4) + rg * 16 + l;
    const int sw = l ^ (rg & 7);

    float4 va[8];

    // Batch 1: passes 0-3 (rows p*16+rg)
    #pragma unroll
    for (int p = 0; p < 4; ++p) {
        va[2 * p]     = ldcs4(base + p * 256);
        va[2 * p + 1] = ldcs4(base + p * 256 + 8);
    }
    #pragma unroll
    for (int p = 0; p < 4; ++p) {
        float4 v0 = va[2 * p], v1 = va[2 * p + 1];
        float dp = v0.x * k0.x + v0.y * k0.y + v0.z * k0.z + v0.w * k0.w
                 + v1.x * k1.x + v1.y * k1.y + v1.z * k1.z + v1.w * k1.w;
        float np = v0.x * v0.x + v0.y * v0.y + v0.z * v0.z + v0.w * v0.w
                 + v1.x * v1.x + v1.y * v1.y + v1.z * v1.z + v1.w * v1.w;
        const int row = p * 16 + rg;
        shdp[(row << 3) + sw] = dp;
        shnp[(row << 3) + sw] = np;
    }

    // Batch 2: passes 4-7
    #pragma unroll
    for (int p = 0; p < 4; ++p) {
        va[2 * p]     = ldcs4(base + (p + 4) * 256);
        va[2 * p + 1] = ldcs4(base + (p + 4) * 256 + 8);
    }
    #pragma unroll
    for (int p = 0; p < 4; ++p) {
        float4 v0 = va[2 * p], v1 = va[2 * p + 1];
        float dp = v0.x * k0.x + v0.y * k0.y + v0.z * k0.z + v0.w * k0.w
                 + v1.x * k1.x + v1.y * k1.y + v1.z * k1.z + v1.w * k1.w;
        float np = v0.x * v0.x + v0.y * v0.y + v0.z * v0.z + v0.w * v0.w
                 + v1.x * v1.x + v1.y * v1.y + v1.z * v1.z + v1.w * v1.w;
        const int row = (p + 4) * 16 + rg;
        shdp[(row << 3) + sw] = dp;
        shnp[(row << 3) + sw] = np;
    }
    __syncthreads();

    // ---- Per-row reduction from swizzled smem (order-independent sum) ----
    const float4* dp4 = reinterpret_cast<const float4*>(&shdp[tid << 3]);
    const float4* np4 = reinterpret_cast<const float4*>(&shnp[tid << 3]);
    float4 d0 = dp4[0], d1 = dp4[1];
    float4 n0 = np4[0], n1 = np4[1];
    float dot = (d0.x + d0.y) + (d0.z + d0.w) + (d1.x + d1.y) + (d1.z + d1.w);
    float nrm = (n0.x + n0.y) + (n0.z + n0.w) + (n1.x + n1.y) + (n1.z + n1.w);

    float mem_norm = fmaxf(sqrtf(nrm), 1e-8f);
    float z = par[0] * ((dot / mem_norm) * inv_kn);

    // ---- Softmax WITHOUT max-subtraction: |z| <= beta <~ 5, exp safe ----
    float e = __expf(z);
    float se = warp_sum(e);
    if (lane == 0) redB[wid] = se;
    __syncthreads();
    float tot = redB[0] + redB[1] + redB[2] + redB[3];
    float wc = e / tot;

    // ---- Interpolate ----
    float g = par[1];
    float wg = g * wc + (1.f - g) * wp;
    shw[tid] = wg;
    __syncthreads();

    // ---- Circular 3-tap shift ----
    float wh = shw[(tid + NN - 1) & (NN - 1)] * par[2]
             + wg * par[3]
             + shw[(tid + 1) & (NN - 1)] * par[4];

    // ---- Sharpen + normalize ----
    float w = __powf(wh, par[5]);
    float sw2 = warp_sum(w);
    if (lane == 0) redA[wid] = sw2;
    __syncthreads();
    float tw = redA[0] + redA[1] + redA[2] + redA[3] + 1e-16f;

    out[(size_t)b * NN + tid] = w / tw;
}

extern "C" void kernel_launch(void* const* d_in, const int* in_sizes, int n_in,
                              void* d_out, int out_size) {
    const float* memory  = (const float*)d_in[0];  // [B, N, M]
    const float* k       = (const float*)d_in[1];  // [B, M]
    const float* beta    = (const float*)d_in[2];  // [B, 1]
    const float* g       = (const float*)d_in[3];  // [B, 1]
    const float* s       = (const float*)d_in[4];  // [B, 3]
    const float* gamma   = (const float*)d_in[5];  // [B, 1]
    const float* w_prev  = (const float*)d_in[6];  // [B, N]
    float* out = (float*)d_out;

    int B = in_sizes[0] / (NN * MM);
    rom_kernel<<<B, 128>>>(memory, k, beta, g, s, gamma, w_prev, out);
}

// round 6
// speedup vs baseline: 1.5906x; 1.0655x over previous
#include <cuda_runtime.h>
#include <math.h>

#define NN 128
#define MM 64
#define UNROLL 4

__device__ __forceinline__ float softplus_f(float x) {
    return x > 0.f ? x + log1pf(expf(-x)) : log1pf(expf(x));
}

__device__ __forceinline__ float warp_sum(float v) {
    #pragma unroll
    for (int o = 16; o > 0; o >>= 1) v += __shfl_xor_sync(0xffffffffu, v, o);
    return v;
}

__device__ __forceinline__ float4 ldcs4(const float4* p) {
    return __ldcs(p);
}

__global__ __launch_bounds__(128, 8) void rom_kernel(
    const float* __restrict__ memory,   // [B, N, M]
    const float* __restrict__ key,      // [B, M]
    const float* __restrict__ beta_in,  // [B, 1]
    const float* __restrict__ g_in,     // [B, 1]
    const float* __restrict__ s_in,     // [B, 3]
    const float* __restrict__ gamma_in, // [B, 1]
    const float* __restrict__ w_prev,   // [B, N]
    float* __restrict__ out)            // [B, N]
{
    __shared__ float shdp[2][NN * 8];   // per-row dot partials (double-buffered)
    __shared__ float shnp[2][NN * 8];   // per-row norm partials
    __shared__ float shw[NN];
    __shared__ float redA[4], redB[4];
    __shared__ float par[UNROLL][8];    // beta, g, s0, s1, s2, gamma

    const int b0   = blockIdx.x * UNROLL;
    const int tid  = threadIdx.x;
    const int lane = tid & 31;
    const int wid  = tid >> 5;
    const int l    = tid & 7;
    const int rg   = tid >> 3;
    const int sw   = l ^ (rg & 7);

    if (tid < UNROLL) {
        const int bb = b0 + tid;
        par[tid][0] = softplus_f(beta_in[bb]);
        par[tid][1] = 1.f / (1.f + __expf(-g_in[bb]));
        float s0 = s_in[bb * 3 + 0], s1 = s_in[bb * 3 + 1], s2 = s_in[bb * 3 + 2];
        float sm = fmaxf(s0, fmaxf(s1, s2));
        float e0 = __expf(s0 - sm), e1 = __expf(s1 - sm), e2 = __expf(s2 - sm);
        float inv = 1.f / (e0 + e1 + e2);
        par[tid][2] = e0 * inv; par[tid][3] = e1 * inv; par[tid][4] = e2 * inv;
        par[tid][5] = 1.f + softplus_f(gamma_in[bb]);
    }

    float wp[UNROLL];
    #pragma unroll
    for (int j = 0; j < UNROLL; ++j)
        wp[j] = w_prev[(size_t)(b0 + j) * NN + tid];

    const float4* mem4 = reinterpret_cast<const float4*>(memory);
    const float4* key4 = reinterpret_cast<const float4*>(key);

    // Helper lambdas (inlined): issue the 8-LDG front batch for 4 rows
    // (rows p*16+rg for p in [p0, p0+4)), chunks l and l+8 of each row.
    float4 va[8];
    auto issue = [&](int bb, int p0) {
        const float4* base = mem4 + (size_t)bb * (NN * MM / 4) + rg * 16 + l;
        #pragma unroll
        for (int p = 0; p < 4; ++p) {
            va[2 * p]     = ldcs4(base + (p0 + p) * 256);
            va[2 * p + 1] = ldcs4(base + (p0 + p) * 256 + 8);
        }
    };
    auto compute = [&](int buf, int p0, const float4& k0, const float4& k1) {
        #pragma unroll
        for (int q = 0; q < 4; ++q) {
            float4 v0 = va[2 * q], v1 = va[2 * q + 1];
            float dp = v0.x * k0.x + v0.y * k0.y + v0.z * k0.z + v0.w * k0.w
                     + v1.x * k1.x + v1.y * k1.y + v1.z * k1.z + v1.w * k1.w;
            float np = v0.x * v0.x + v0.y * v0.y + v0.z * v0.z + v0.w * v0.w
                     + v1.x * v1.x + v1.y * v1.y + v1.z * v1.z + v1.w * v1.w;
            const int row = (p0 + q) * 16 + rg;
            shdp[buf][(row << 3) + sw] = dp;
            shnp[buf][(row << 3) + sw] = np;
        }
    };

    // ---- Prologue: key + first half-tile of batch 0 ----
    float4 k0 = key4[(size_t)b0 * (MM / 4) + l];
    float4 k1 = key4[(size_t)b0 * (MM / 4) + l + 8];
    issue(b0, 0);

    float knp = k0.x * k0.x + k0.y * k0.y + k0.z * k0.z + k0.w * k0.w
              + k1.x * k1.x + k1.y * k1.y + k1.z * k1.z + k1.w * k1.w;
    #pragma unroll
    for (int o = 4; o > 0; o >>= 1) knp += __shfl_xor_sync(0xffffffffu, knp, o);
    float inv_kn = 1.f / fmaxf(sqrtf(knp), 1e-8f);

    #pragma unroll
    for (int j = 0; j < UNROLL; ++j) {
        const int buf = j & 1;
        const int bb  = b0 + j;

        // half 1 compute (va holds rows 0..63 chunk-pairs); then issue half 2
        float4 tmp[8];
        {
            const float4* base = mem4 + (size_t)bb * (NN * MM / 4) + rg * 16 + l;
            #pragma unroll
            for (int p = 0; p < 4; ++p) {      // issue half 2 FIRST (independent)
                tmp[2 * p]     = ldcs4(base + (p + 4) * 256);
                tmp[2 * p + 1] = ldcs4(base + (p + 4) * 256 + 8);
            }
        }
        compute(buf, 0, k0, k1);
        #pragma unroll
        for (int p = 0; p < 8; ++p) va[p] = tmp[p];
        compute(buf, 4, k0, k1);

        // prefetch key + first half-tile of batch j+1 BEFORE the epilogue
        float inv_kn_nxt = inv_kn;
        if (j + 1 < UNROLL) {
            const int bn = bb + 1;
            k0 = key4[(size_t)bn * (MM / 4) + l];
            k1 = key4[(size_t)bn * (MM / 4) + l + 8];
            issue(bn, 0);
            float kn = k0.x * k0.x + k0.y * k0.y + k0.z * k0.z + k0.w * k0.w
                     + k1.x * k1.x + k1.y * k1.y + k1.z * k1.z + k1.w * k1.w;
            #pragma unroll
            for (int o = 4; o > 0; o >>= 1) kn += __shfl_xor_sync(0xffffffffu, kn, o);
            inv_kn_nxt = 1.f / fmaxf(sqrtf(kn), 1e-8f);
        }
        __syncthreads();

        // ---- Epilogue (batch j) with batch j+1 loads in flight ----
        const float4* dp4 = reinterpret_cast<const float4*>(&shdp[buf][tid << 3]);
        const float4* np4 = reinterpret_cast<const float4*>(&shnp[buf][tid << 3]);
        float4 d0 = dp4[0], d1 = dp4[1];
        float4 n0 = np4[0], n1 = np4[1];
        float dot = (d0.x + d0.y) + (d0.z + d0.w) + (d1.x + d1.y) + (d1.z + d1.w);
        float nrm = (n0.x + n0.y) + (n0.z + n0.w) + (n1.x + n1.y) + (n1.z + n1.w);

        float mem_norm = fmaxf(sqrtf(nrm), 1e-8f);
        float z = par[j][0] * ((dot / mem_norm) * inv_kn);

        float e = __expf(z);
        float se = warp_sum(e);
        if (lane == 0) redB[wid] = se;
        __syncthreads();
        float tot = redB[0] + redB[1] + redB[2] + redB[3];
        float wc = e / tot;

        float g = par[j][1];
        float wg = g * wc + (1.f - g) * wp[j];
        shw[tid] = wg;
        __syncthreads();

        float wh = shw[(tid + NN - 1) & (NN - 1)] * par[j][2]
                 + wg * par[j][3]
                 + shw[(tid + 1) & (NN - 1)] * par[j][4];

        float w = __powf(wh, par[j][5]);
        float sw2 = warp_sum(w);
        if (lane == 0) redA[wid] = sw2;
        __syncthreads();
        float tw = redA[0] + redA[1] + redA[2] + redA[3] + 1e-16f;

        out[(size_t)bb * NN + tid] = w / tw;

        inv_kn = inv_kn_nxt;
    }
}

extern "C" void kernel_launch(void* const* d_in, const int* in_sizes, int n_in,
                              void* d_out, int out_size) {
    const float* memory  = (const float*)d_in[0];  // [B, N, M]
    const float* k       = (const float*)d_in[1];  // [B, M]
    const float* beta    = (const float*)d_in[2];  // [B, 1]
    const float* g       = (const float*)d_in[3];  // [B, 1]
    const float* s       = (const float*)d_in[4];  // [B, 3]
    const float* gamma   = (const float*)d_in[5];  // [B, 1]
    const float* w_prev  = (const float*)d_in[6];  // [B, N]
    float* out = (float*)d_out;

    int B = in_sizes[0] / (NN * MM);
    rom_kernel<<<B / UNROLL, 128>>>(memory, k, beta, g, s, gamma, w_prev, out);
}